// round 3
// baseline (speedup 1.0000x reference)
#include <cuda_runtime.h>
#include <math.h>

#define TOKENS 8192
#define DM 512
#define DFF 2048
#define SEQ 2048
#define NH 8
#define DH 64

// Scratch (allocation-free rule: __device__ globals)
__device__ float g_xn[TOKENS * DM];
__device__ float g_qkv[TOKENS * 3 * DM];
__device__ float g_x1[TOKENS * DM];
__device__ float g_xn2[TOKENS * DM];
__device__ float g_hbuf[TOKENS * DFF];

// ---------------------------------------------------------------------------
// LayerNorm: one block (128 threads) per token row of 512
// ---------------------------------------------------------------------------
__global__ __launch_bounds__(128) void ln_kernel(
    const float* __restrict__ x, const float* __restrict__ g,
    const float* __restrict__ beta, float* __restrict__ out) {
    int row = blockIdx.x;
    int tid = threadIdx.x;
    const float4* xr = reinterpret_cast<const float4*>(x + (size_t)row * DM);
    float4 v = xr[tid];
    float s = v.x + v.y + v.z + v.w;
    float sq = v.x * v.x + v.y * v.y + v.z * v.z + v.w * v.w;
#pragma unroll
    for (int off = 16; off > 0; off >>= 1) {
        s  += __shfl_xor_sync(0xffffffffu, s, off);
        sq += __shfl_xor_sync(0xffffffffu, sq, off);
    }
    __shared__ float ss[4], ssq[4];
    int wid = tid >> 5, lane = tid & 31;
    if (lane == 0) { ss[wid] = s; ssq[wid] = sq; }
    __syncthreads();
    s  = ss[0] + ss[1] + ss[2] + ss[3];
    sq = ssq[0] + ssq[1] + ssq[2] + ssq[3];
    float mean = s * (1.0f / DM);
    float var = sq * (1.0f / DM) - mean * mean;
    float inv = rsqrtf(var + 1e-5f);
    float4 gv = reinterpret_cast<const float4*>(g)[tid];
    float4 bv = reinterpret_cast<const float4*>(beta)[tid];
    float4 o;
    o.x = (v.x - mean) * inv * gv.x + bv.x;
    o.y = (v.y - mean) * inv * gv.y + bv.y;
    o.z = (v.z - mean) * inv * gv.z + bv.z;
    o.w = (v.w - mean) * inv * gv.w + bv.w;
    reinterpret_cast<float4*>(out + (size_t)row * DM)[tid] = o;
}

// ---------------------------------------------------------------------------
// Tiled fp32 GEMM: C[M,N] = A[M,K] @ B[K,N] + bias (+relu) (+residual)
// Block tile 128x64, 256 threads, 8x4 per thread, K-step 16.
// M,N,K assumed multiples of 128/64/16.
// ---------------------------------------------------------------------------
template <int RELU, int RES>
__global__ __launch_bounds__(256) void gemm_kernel(
    const float* __restrict__ A, int lda,
    const float* __restrict__ B, int ldb,
    const float* __restrict__ bias,
    const float* __restrict__ res,
    float* __restrict__ C, int ldc, int K) {
    __shared__ float As[16][128];   // [k][m]
    __shared__ float Bs[16][64];    // [k][n]
    int tid = threadIdx.x;
    int tx = tid & 15, ty = tid >> 4;
    int row0 = blockIdx.y * 128;
    int col0 = blockIdx.x * 64;

    float acc[8][4];
#pragma unroll
    for (int r = 0; r < 8; ++r)
#pragma unroll
        for (int c = 0; c < 4; ++c) acc[r][c] = 0.0f;

    for (int k0 = 0; k0 < K; k0 += 16) {
        // A tile: 128x16, loaded as float4 along K, stored k-major
#pragma unroll
        for (int it = 0; it < 2; ++it) {
            int f = it * 256 + tid;
            int m = f & 127, kc = f >> 7;  // kc in 0..3
            float4 v = *reinterpret_cast<const float4*>(
                A + (size_t)(row0 + m) * lda + k0 + kc * 4);
            As[kc * 4 + 0][m] = v.x;
            As[kc * 4 + 1][m] = v.y;
            As[kc * 4 + 2][m] = v.z;
            As[kc * 4 + 3][m] = v.w;
        }
        // B tile: 16x64
        {
            int kr = tid >> 4, c4 = tid & 15;
            float4 v = *reinterpret_cast<const float4*>(
                B + (size_t)(k0 + kr) * ldb + col0 + c4 * 4);
            *reinterpret_cast<float4*>(&Bs[kr][c4 * 4]) = v;
        }
        __syncthreads();
#pragma unroll
        for (int kk = 0; kk < 16; ++kk) {
            float4 a0 = *reinterpret_cast<float4*>(&As[kk][ty * 8]);
            float4 a1 = *reinterpret_cast<float4*>(&As[kk][ty * 8 + 4]);
            float4 b4 = *reinterpret_cast<float4*>(&Bs[kk][tx * 4]);
            float av[8] = {a0.x, a0.y, a0.z, a0.w, a1.x, a1.y, a1.z, a1.w};
            float bv[4] = {b4.x, b4.y, b4.z, b4.w};
#pragma unroll
            for (int r = 0; r < 8; ++r)
#pragma unroll
                for (int c = 0; c < 4; ++c)
                    acc[r][c] = fmaf(av[r], bv[c], acc[r][c]);
        }
        __syncthreads();
    }

    float4 bb = *reinterpret_cast<const float4*>(bias + col0 + tx * 4);
#pragma unroll
    for (int r = 0; r < 8; ++r) {
        int row = row0 + ty * 8 + r;
        float4 v;
        v.x = acc[r][0] + bb.x;
        v.y = acc[r][1] + bb.y;
        v.z = acc[r][2] + bb.z;
        v.w = acc[r][3] + bb.w;
        if (RELU) {
            v.x = fmaxf(v.x, 0.0f); v.y = fmaxf(v.y, 0.0f);
            v.z = fmaxf(v.z, 0.0f); v.w = fmaxf(v.w, 0.0f);
        }
        if (RES) {
            float4 rv = *reinterpret_cast<const float4*>(
                res + (size_t)row * ldc + col0 + tx * 4);
            v.x += rv.x; v.y += rv.y; v.z += rv.z; v.w += rv.w;
        }
        *reinterpret_cast<float4*>(C + (size_t)row * ldc + col0 + tx * 4) = v;
    }
}

// ---------------------------------------------------------------------------
// Sigmoid attention, streamed (no softmax normalization -> no rescaling).
// Block: (s_tile of 64 rows) x (b,h). Per t-tile of 64:
//   S = Q @ K^T * scale ; P = sigmoid(S) ; O += P @ V
// Residual add of x fused into epilogue (writes x1).
// ---------------------------------------------------------------------------
__global__ __launch_bounds__(256) void attn_kernel(
    const float* __restrict__ qkv, const float* __restrict__ x,
    float* __restrict__ x1) {
    __shared__ float Qt[64][64];  // [d][i]  (transposed Q tile)
    __shared__ float KV[64][64];  // Kt[d][j], later reused as Vs[t][j]
    __shared__ float Ss[64][64];  // [i][t]  sigmoid(scores)

    int tid = threadIdx.x;
    int tx = tid & 15, ty = tid >> 4;
    int s0 = blockIdx.x * 64;
    int b = blockIdx.y >> 3, h = blockIdx.y & 7;

    const float* qb = qkv + ((size_t)b * SEQ) * (3 * DM) + h * DH;
    const float* kb = qb + DM;
    const float* vb = qb + 2 * DM;

    // Load Q tile transposed: Qt[d][i]
#pragma unroll
    for (int it = 0; it < 4; ++it) {
        int f = it * 256 + tid;
        int i = f & 63, dc = f >> 6;  // dc 0..15
        float4 v = *reinterpret_cast<const float4*>(
            qb + (size_t)(s0 + i) * (3 * DM) + dc * 4);
        Qt[dc * 4 + 0][i] = v.x;
        Qt[dc * 4 + 1][i] = v.y;
        Qt[dc * 4 + 2][i] = v.z;
        Qt[dc * 4 + 3][i] = v.w;
    }

    float o[4][4];
#pragma unroll
    for (int r = 0; r < 4; ++r)
#pragma unroll
        for (int c = 0; c < 4; ++c) o[r][c] = 0.0f;

    const float scale = 0.04419417382415922f;  // 1/sqrt(512)

    for (int t0 = 0; t0 < SEQ; t0 += 64) {
        __syncthreads();  // prev-iter Vs reads done (also fences Qt stores on iter 0)
        // Load K tile transposed: KV[d][j]
#pragma unroll
        for (int it = 0; it < 4; ++it) {
            int f = it * 256 + tid;
            int j = f & 63, dc = f >> 6;
            float4 v = *reinterpret_cast<const float4*>(
                kb + (size_t)(t0 + j) * (3 * DM) + dc * 4);
            KV[dc * 4 + 0][j] = v.x;
            KV[dc * 4 + 1][j] = v.y;
            KV[dc * 4 + 2][j] = v.z;
            KV[dc * 4 + 3][j] = v.w;
        }
        __syncthreads();

        float sacc[4][4];
#pragma unroll
        for (int r = 0; r < 4; ++r)
#pragma unroll
            for (int c = 0; c < 4; ++c) sacc[r][c] = 0.0f;

#pragma unroll 8
        for (int d = 0; d < 64; ++d) {
            float4 a = *reinterpret_cast<float4*>(&Qt[d][ty * 4]);
            float4 bb = *reinterpret_cast<float4*>(&KV[d][tx * 4]);
            float av[4] = {a.x, a.y, a.z, a.w};
            float bv[4] = {bb.x, bb.y, bb.z, bb.w};
#pragma unroll
            for (int r = 0; r < 4; ++r)
#pragma unroll
                for (int c = 0; c < 4; ++c)
                    sacc[r][c] = fmaf(av[r], bv[c], sacc[r][c]);
        }
        // sigmoid -> Ss[i][t]
#pragma unroll
        for (int r = 0; r < 4; ++r)
#pragma unroll
            for (int c = 0; c < 4; ++c) {
                float sv = sacc[r][c] * scale;
                Ss[ty * 4 + r][tx * 4 + c] = 1.0f / (1.0f + __expf(-sv));
            }
        __syncthreads();
        // Load V tile (row-major): KV[t][j]
#pragma unroll
        for (int it = 0; it < 4; ++it) {
            int f = it * 256 + tid;
            int c4 = f & 15, t = f >> 4;
            float4 v = *reinterpret_cast<const float4*>(
                vb + (size_t)(t0 + t) * (3 * DM) + c4 * 4);
            *reinterpret_cast<float4*>(&KV[t][c4 * 4]) = v;
        }
        __syncthreads();
        // O += P @ V
#pragma unroll 8
        for (int t = 0; t < 64; ++t) {
            float a0 = Ss[ty * 4 + 0][t];
            float a1 = Ss[ty * 4 + 1][t];
            float a2 = Ss[ty * 4 + 2][t];
            float a3 = Ss[ty * 4 + 3][t];
            float4 bb = *reinterpret_cast<float4*>(&KV[t][tx * 4]);
            float bv[4] = {bb.x, bb.y, bb.z, bb.w};
            float av[4] = {a0, a1, a2, a3};
#pragma unroll
            for (int r = 0; r < 4; ++r)
#pragma unroll
                for (int c = 0; c < 4; ++c)
                    o[r][c] = fmaf(av[r], bv[c], o[r][c]);
        }
    }

    // Epilogue: x1 = x + attn_out (scatter to [token, h*64+dh])
#pragma unroll
    for (int r = 0; r < 4; ++r) {
        int s = s0 + ty * 4 + r;
        size_t base = ((size_t)(b * SEQ + s)) * DM + h * DH + tx * 4;
        float4 xv = *reinterpret_cast<const float4*>(x + base);
        float4 v;
        v.x = xv.x + o[r][0];
        v.y = xv.y + o[r][1];
        v.z = xv.z + o[r][2];
        v.w = xv.w + o[r][3];
        *reinterpret_cast<float4*>(x1 + base) = v;
    }
}

// ---------------------------------------------------------------------------
extern "C" void kernel_launch(void* const* d_in, const int* in_sizes, int n_in,
                              void* d_out, int out_size) {
    const float* x  = (const float*)d_in[0];
    const float* Wq = (const float*)d_in[1];
    const float* bq = (const float*)d_in[2];
    const float* Wk = (const float*)d_in[3];
    const float* bk = (const float*)d_in[4];
    const float* Wv = (const float*)d_in[5];
    const float* bv = (const float*)d_in[6];
    const float* W1 = (const float*)d_in[7];
    const float* b1 = (const float*)d_in[8];
    const float* W2 = (const float*)d_in[9];
    const float* b2 = (const float*)d_in[10];
    const float* g1 = (const float*)d_in[11];
    const float* be1 = (const float*)d_in[12];
    const float* g2 = (const float*)d_in[13];
    const float* be2 = (const float*)d_in[14];
    float* out = (float*)d_out;

    float *xn, *qkv, *x1, *xn2, *hbuf;
    cudaGetSymbolAddress((void**)&xn, g_xn);
    cudaGetSymbolAddress((void**)&qkv, g_qkv);
    cudaGetSymbolAddress((void**)&x1, g_x1);
    cudaGetSymbolAddress((void**)&xn2, g_xn2);
    cudaGetSymbolAddress((void**)&hbuf, g_hbuf);

    // 1. LN1
    ln_kernel<<<TOKENS, 128>>>(x, g1, be1, xn);
    // 2. Q/K/V projections into fused qkv[8192, 1536]
    gemm_kernel<0, 0><<<dim3(DM / 64, TOKENS / 128), 256>>>(
        xn, DM, Wq, DM, bq, nullptr, qkv + 0, 3 * DM, DM);
    gemm_kernel<0, 0><<<dim3(DM / 64, TOKENS / 128), 256>>>(
        xn, DM, Wk, DM, bk, nullptr, qkv + DM, 3 * DM, DM);
    gemm_kernel<0, 0><<<dim3(DM / 64, TOKENS / 128), 256>>>(
        xn, DM, Wv, DM, bv, nullptr, qkv + 2 * DM, 3 * DM, DM);
    // 3. Sigmoid attention + residual -> x1
    attn_kernel<<<dim3(SEQ / 64, 4 * NH), 256>>>(qkv, x, x1);
    // 4. LN2
    ln_kernel<<<TOKENS, 128>>>(x1, g2, be2, xn2);
    // 5. FFN1 + ReLU
    gemm_kernel<1, 0><<<dim3(DFF / 64, TOKENS / 128), 256>>>(
        xn2, DM, W1, DFF, b1, nullptr, hbuf, DFF, DM);
    // 6. FFN2 + bias + residual -> out
    gemm_kernel<0, 1><<<dim3(DM / 64, TOKENS / 128), 256>>>(
        hbuf, DFF, W2, DM, b2, x1, out, DM, DFF);
}

// round 7
// speedup vs baseline: 2.9739x; 2.9739x over previous
#include <cuda_runtime.h>
#include <math.h>

#define TOKENS 8192
#define DM 512
#define DFF 2048
#define SEQ 2048
#define NH 8
#define DH 64

// Scratch (allocation-free rule: __device__ globals)
__device__ float g_xn[TOKENS * DM];
__device__ float g_qkv[TOKENS * 3 * DM];
__device__ float g_x1[TOKENS * DM];
__device__ float g_xn2[TOKENS * DM];
__device__ float g_hbuf[TOKENS * DFF];
__device__ float g_wqkv[DM * 3 * DM];
__device__ float g_bqkv[3 * DM];

// ---------------------------------------------------------------------------
// tf32 helpers
// ---------------------------------------------------------------------------
__device__ __forceinline__ unsigned f2tf(float x) {
    unsigned r;
    asm("cvt.rna.tf32.f32 %0, %1;" : "=r"(r) : "f"(x));
    return r;
}
__device__ __forceinline__ uint4 f2tf4(float4 v) {
    uint4 r;
    r.x = f2tf(v.x); r.y = f2tf(v.y); r.z = f2tf(v.z); r.w = f2tf(v.w);
    return r;
}
__device__ __forceinline__ void mma8(float* c, const unsigned* a, const unsigned* b) {
    asm volatile(
        "mma.sync.aligned.m16n8k8.row.col.f32.tf32.tf32.f32 "
        "{%0,%1,%2,%3}, {%4,%5,%6,%7}, {%8,%9}, {%0,%1,%2,%3};\n"
        : "+f"(c[0]), "+f"(c[1]), "+f"(c[2]), "+f"(c[3])
        : "r"(a[0]), "r"(a[1]), "r"(a[2]), "r"(a[3]), "r"(b[0]), "r"(b[1]));
}

// ---------------------------------------------------------------------------
// LayerNorm: one block (128 threads) per token row of 512
// ---------------------------------------------------------------------------
__global__ __launch_bounds__(128) void ln_kernel(
    const float* __restrict__ x, const float* __restrict__ g,
    const float* __restrict__ beta, float* __restrict__ out) {
    int row = blockIdx.x;
    int tid = threadIdx.x;
    const float4* xr = reinterpret_cast<const float4*>(x + (size_t)row * DM);
    float4 v = xr[tid];
    float s = v.x + v.y + v.z + v.w;
    float sq = v.x * v.x + v.y * v.y + v.z * v.z + v.w * v.w;
#pragma unroll
    for (int off = 16; off > 0; off >>= 1) {
        s  += __shfl_xor_sync(0xffffffffu, s, off);
        sq += __shfl_xor_sync(0xffffffffu, sq, off);
    }
    __shared__ float ss[4], ssq[4];
    int wid = tid >> 5, lane = tid & 31;
    if (lane == 0) { ss[wid] = s; ssq[wid] = sq; }
    __syncthreads();
    s  = ss[0] + ss[1] + ss[2] + ss[3];
    sq = ssq[0] + ssq[1] + ssq[2] + ssq[3];
    float mean = s * (1.0f / DM);
    float var = sq * (1.0f / DM) - mean * mean;
    float inv = rsqrtf(var + 1e-5f);
    float4 gv = reinterpret_cast<const float4*>(g)[tid];
    float4 bv = reinterpret_cast<const float4*>(beta)[tid];
    float4 o;
    o.x = (v.x - mean) * inv * gv.x + bv.x;
    o.y = (v.y - mean) * inv * gv.y + bv.y;
    o.z = (v.z - mean) * inv * gv.z + bv.z;
    o.w = (v.w - mean) * inv * gv.w + bv.w;
    reinterpret_cast<float4*>(out + (size_t)row * DM)[tid] = o;
}

// ---------------------------------------------------------------------------
// Pack Wq|Wk|Wv -> [512][1536] and biases -> [1536]
// ---------------------------------------------------------------------------
__global__ __launch_bounds__(256) void pack_qkv_kernel(
    const float* __restrict__ Wq, const float* __restrict__ Wk,
    const float* __restrict__ Wv, const float* __restrict__ bq,
    const float* __restrict__ bk, const float* __restrict__ bv,
    float* __restrict__ W, float* __restrict__ bias) {
    int idx = blockIdx.x * 256 + threadIdx.x;  // over 512*384 float4
    int row = idx / 384;
    int c4 = idx - row * 384;
    const float* src = (c4 < 128) ? Wq : (c4 < 256 ? Wk : Wv);
    int cc = (c4 & 127) * 4;
    float4 v = *reinterpret_cast<const float4*>(src + (size_t)row * DM + cc);
    *reinterpret_cast<float4*>(W + (size_t)row * (3 * DM) + c4 * 4) = v;
    if (idx < 384) {
        const float* bsrc = (idx < 128) ? bq : (idx < 256 ? bk : bv);
        *reinterpret_cast<float4*>(bias + idx * 4) =
            *reinterpret_cast<const float4*>(bsrc + (idx & 127) * 4);
    }
}

// ---------------------------------------------------------------------------
// tf32 tensor-core GEMM: C[M,N] = A[M,K] @ B[K,N] + bias (+relu) (+residual)
// Block 128x128x32, 256 threads (8 warps, 2x4), warp tile 64x32 via m16n8k8.
// ---------------------------------------------------------------------------
#define BM 128
#define BN 128
#define BK 32
#define LDA_S 36
#define LDB_S 136

template <int RELU, int RES>
__global__ __launch_bounds__(256, 2) void mma_gemm(
    const float* __restrict__ A, int lda,
    const float* __restrict__ B, int ldb,
    const float* __restrict__ bias,
    const float* __restrict__ res,
    float* __restrict__ C, int ldc, int K) {
    __shared__ unsigned As[BM * LDA_S];
    __shared__ unsigned Bs[BK * LDB_S];
    int tid = threadIdx.x;
    int lane = tid & 31, wid = tid >> 5;
    int g = lane >> 2, tg = lane & 3;
    int wm = (wid >> 2) * 64;
    int wn = (wid & 3) * 32;
    int row0 = blockIdx.y * BM, col0 = blockIdx.x * BN;

    float acc[4][4][4];
#pragma unroll
    for (int i = 0; i < 4; ++i)
#pragma unroll
        for (int j = 0; j < 4; ++j)
#pragma unroll
            for (int l = 0; l < 4; ++l) acc[i][j][l] = 0.0f;

    for (int k0 = 0; k0 < K; k0 += BK) {
#pragma unroll
        for (int p = 0; p < 4; ++p) {
            int f = p * 256 + tid;
            int r = f >> 3, k4 = f & 7;
            float4 v = *reinterpret_cast<const float4*>(
                A + (size_t)(row0 + r) * lda + k0 + k4 * 4);
            *reinterpret_cast<uint4*>(&As[r * LDA_S + k4 * 4]) = f2tf4(v);
        }
#pragma unroll
        for (int p = 0; p < 4; ++p) {
            int f = p * 256 + tid;
            int kr = f >> 5, n4 = f & 31;
            float4 v = *reinterpret_cast<const float4*>(
                B + (size_t)(k0 + kr) * ldb + col0 + n4 * 4);
            *reinterpret_cast<uint4*>(&Bs[kr * LDB_S + n4 * 4]) = f2tf4(v);
        }
        __syncthreads();
#pragma unroll
        for (int kk = 0; kk < 4; ++kk) {
            int kb = kk * 8;
            unsigned Af[4][4], Bf[4][2];
#pragma unroll
            for (int mt = 0; mt < 4; ++mt) {
                int r = wm + mt * 16 + g;
                Af[mt][0] = As[r * LDA_S + kb + tg];
                Af[mt][1] = As[(r + 8) * LDA_S + kb + tg];
                Af[mt][2] = As[r * LDA_S + kb + 4 + tg];
                Af[mt][3] = As[(r + 8) * LDA_S + kb + 4 + tg];
            }
#pragma unroll
            for (int nt = 0; nt < 4; ++nt) {
                int c = wn + nt * 8 + g;
                Bf[nt][0] = Bs[(kb + tg) * LDB_S + c];
                Bf[nt][1] = Bs[(kb + 4 + tg) * LDB_S + c];
            }
#pragma unroll
            for (int mt = 0; mt < 4; ++mt)
#pragma unroll
                for (int nt = 0; nt < 4; ++nt)
                    mma8(acc[mt][nt], Af[mt], Bf[nt]);
        }
        __syncthreads();
    }

#pragma unroll
    for (int nt = 0; nt < 4; ++nt) {
        int c = col0 + wn + nt * 8 + tg * 2;
        float b0 = bias[c], b1 = bias[c + 1];
#pragma unroll
        for (int mt = 0; mt < 4; ++mt) {
#pragma unroll
            for (int hh = 0; hh < 2; ++hh) {
                int r = row0 + wm + mt * 16 + g + hh * 8;
                float v0 = acc[mt][nt][hh * 2 + 0] + b0;
                float v1 = acc[mt][nt][hh * 2 + 1] + b1;
                if (RELU) { v0 = fmaxf(v0, 0.0f); v1 = fmaxf(v1, 0.0f); }
                if (RES) {
                    float2 rv = *reinterpret_cast<const float2*>(
                        res + (size_t)r * ldc + c);
                    v0 += rv.x; v1 += rv.y;
                }
                *reinterpret_cast<float2*>(C + (size_t)r * ldc + c) =
                    make_float2(v0, v1);
            }
        }
    }
}

// ---------------------------------------------------------------------------
// Sigmoid attention with tf32 tensor cores.
// Block: 128 q-rows x (b,h); stream t-tiles of 64.
//   S = Q K^T * scale ; P = sigmoid(S) (staged in smem as tf32) ; O += P V
// Residual x fused into epilogue (writes x1).
// ---------------------------------------------------------------------------
#define LDQ 68
#define LDKV 72
#define LDS_S 68
#define ATTN_SMEM ((128 * LDQ + 64 * LDKV + 128 * LDS_S) * 4)

__global__ __launch_bounds__(256, 2) void attn_kernel(
    const float* __restrict__ qkv, const float* __restrict__ x,
    float* __restrict__ x1) {
    extern __shared__ unsigned sm[];
    unsigned* Qs = sm;                   // [128][LDQ]
    unsigned* KV = sm + 128 * LDQ;       // [64][LDKV]  (K tile, then V tile)
    unsigned* Ss = KV + 64 * LDKV;       // [128][LDS_S]

    int tid = threadIdx.x;
    int lane = tid & 31, wid = tid >> 5;
    int g = lane >> 2, tg = lane & 3;
    int wm = (wid >> 2) * 64;   // warp q-row offset (2 warps)
    int wn = (wid & 3) * 16;    // warp col offset (4 warps)
    int s0 = blockIdx.x * 128;
    int b = blockIdx.y >> 3, h = blockIdx.y & 7;

    const float* qb = qkv + (size_t)b * SEQ * (3 * DM) + h * DH;
    const float* kb = qb + DM;
    const float* vb = qb + 2 * DM;

    // Q tile [128][64] -> Qs (tf32)
#pragma unroll
    for (int p = 0; p < 8; ++p) {
        int f = p * 256 + tid;
        int r = f >> 4, d4 = f & 15;
        float4 v = *reinterpret_cast<const float4*>(
            qb + (size_t)(s0 + r) * (3 * DM) + d4 * 4);
        *reinterpret_cast<uint4*>(&Qs[r * LDQ + d4 * 4]) = f2tf4(v);
    }

    float of[4][2][4];
#pragma unroll
    for (int i = 0; i < 4; ++i)
#pragma unroll
        for (int j = 0; j < 2; ++j)
#pragma unroll
            for (int l = 0; l < 4; ++l) of[i][j][l] = 0.0f;

    const float scale = 0.04419417382415922f;  // 1/sqrt(512)

    for (int t0 = 0; t0 < SEQ; t0 += 64) {
        __syncthreads();  // prev PV reads of KV/Ss done (also fences Qs, iter 0)
        // K tile [64][64] -> KV
#pragma unroll
        for (int p = 0; p < 4; ++p) {
            int f = p * 256 + tid;
            int r = f >> 4, d4 = f & 15;
            float4 v = *reinterpret_cast<const float4*>(
                kb + (size_t)(t0 + r) * (3 * DM) + d4 * 4);
            *reinterpret_cast<uint4*>(&KV[r * LDKV + d4 * 4]) = f2tf4(v);
        }
        __syncthreads();

        // S = Q @ K^T  (M=128 q, N=64 t, K=64 d)
        float sc[4][2][4];
#pragma unroll
        for (int i = 0; i < 4; ++i)
#pragma unroll
            for (int j = 0; j < 2; ++j)
#pragma unroll
                for (int l = 0; l < 4; ++l) sc[i][j][l] = 0.0f;
#pragma unroll
        for (int kk = 0; kk < 8; ++kk) {
            int kb8 = kk * 8;
            unsigned Af[4][4], Bf[2][2];
#pragma unroll
            for (int mt = 0; mt < 4; ++mt) {
                int r = wm + mt * 16 + g;
                Af[mt][0] = Qs[r * LDQ + kb8 + tg];
                Af[mt][1] = Qs[(r + 8) * LDQ + kb8 + tg];
                Af[mt][2] = Qs[r * LDQ + kb8 + 4 + tg];
                Af[mt][3] = Qs[(r + 8) * LDQ + kb8 + 4 + tg];
            }
#pragma unroll
            for (int nt = 0; nt < 2; ++nt) {
                int c = wn + nt * 8 + g;   // t index
                Bf[nt][0] = KV[c * LDKV + kb8 + tg];
                Bf[nt][1] = KV[c * LDKV + kb8 + 4 + tg];
            }
#pragma unroll
            for (int mt = 0; mt < 4; ++mt)
#pragma unroll
                for (int nt = 0; nt < 2; ++nt)
                    mma8(sc[mt][nt], Af[mt], Bf[nt]);
        }
        // sigmoid -> Ss (tf32)
#pragma unroll
        for (int mt = 0; mt < 4; ++mt)
#pragma unroll
            for (int nt = 0; nt < 2; ++nt) {
                int r = wm + mt * 16 + g;
                int c = wn + nt * 8 + tg * 2;
                uint2 p0, p1;
                p0.x = f2tf(1.0f / (1.0f + __expf(-sc[mt][nt][0] * scale)));
                p0.y = f2tf(1.0f / (1.0f + __expf(-sc[mt][nt][1] * scale)));
                p1.x = f2tf(1.0f / (1.0f + __expf(-sc[mt][nt][2] * scale)));
                p1.y = f2tf(1.0f / (1.0f + __expf(-sc[mt][nt][3] * scale)));
                *reinterpret_cast<uint2*>(&Ss[r * LDS_S + c]) = p0;
                *reinterpret_cast<uint2*>(&Ss[(r + 8) * LDS_S + c]) = p1;
            }
        __syncthreads();  // Ss ready; KV (K) reads done

        // V tile [64][64] -> KV
#pragma unroll
        for (int p = 0; p < 4; ++p) {
            int f = p * 256 + tid;
            int r = f >> 4, d4 = f & 15;
            float4 v = *reinterpret_cast<const float4*>(
                vb + (size_t)(t0 + r) * (3 * DM) + d4 * 4);
            *reinterpret_cast<uint4*>(&KV[r * LDKV + d4 * 4]) = f2tf4(v);
        }
        __syncthreads();

        // O += P @ V  (M=128 q, N=64 d, K=64 t)
#pragma unroll
        for (int kk = 0; kk < 8; ++kk) {
            int kb8 = kk * 8;
            unsigned Af[4][4], Bf[2][2];
#pragma unroll
            for (int mt = 0; mt < 4; ++mt) {
                int r = wm + mt * 16 + g;
                Af[mt][0] = Ss[r * LDS_S + kb8 + tg];
                Af[mt][1] = Ss[(r + 8) * LDS_S + kb8 + tg];
                Af[mt][2] = Ss[r * LDS_S + kb8 + 4 + tg];
                Af[mt][3] = Ss[(r + 8) * LDS_S + kb8 + 4 + tg];
            }
#pragma unroll
            for (int nt = 0; nt < 2; ++nt) {
                int c = wn + nt * 8 + g;   // d index
                Bf[nt][0] = KV[(kb8 + tg) * LDKV + c];
                Bf[nt][1] = KV[(kb8 + 4 + tg) * LDKV + c];
            }
#pragma unroll
            for (int mt = 0; mt < 4; ++mt)
#pragma unroll
                for (int nt = 0; nt < 2; ++nt)
                    mma8(of[mt][nt], Af[mt], Bf[nt]);
        }
    }

    // Epilogue: x1 = x + attn_out
#pragma unroll
    for (int mt = 0; mt < 4; ++mt)
#pragma unroll
        for (int nt = 0; nt < 2; ++nt)
#pragma unroll
            for (int hh = 0; hh < 2; ++hh) {
                int r = s0 + wm + mt * 16 + g + hh * 8;
                int c = h * DH + wn + nt * 8 + tg * 2;
                size_t base = ((size_t)(b * SEQ) + r) * DM + c;
                float2 xv = *reinterpret_cast<const float2*>(x + base);
                float2 o = make_float2(xv.x + of[mt][nt][hh * 2 + 0],
                                       xv.y + of[mt][nt][hh * 2 + 1]);
                *reinterpret_cast<float2*>(x1 + base) = o;
            }
}

// ---------------------------------------------------------------------------
extern "C" void kernel_launch(void* const* d_in, const int* in_sizes, int n_in,
                              void* d_out, int out_size) {
    const float* x  = (const float*)d_in[0];
    const float* Wq = (const float*)d_in[1];
    const float* bq = (const float*)d_in[2];
    const float* Wk = (const float*)d_in[3];
    const float* bk = (const float*)d_in[4];
    const float* Wv = (const float*)d_in[5];
    const float* bv = (const float*)d_in[6];
    const float* W1 = (const float*)d_in[7];
    const float* b1 = (const float*)d_in[8];
    const float* W2 = (const float*)d_in[9];
    const float* b2 = (const float*)d_in[10];
    const float* g1 = (const float*)d_in[11];
    const float* be1 = (const float*)d_in[12];
    const float* g2 = (const float*)d_in[13];
    const float* be2 = (const float*)d_in[14];
    float* out = (float*)d_out;

    float *xn, *qkv, *x1, *xn2, *hbuf, *wqkv, *bqkv;
    cudaGetSymbolAddress((void**)&xn, g_xn);
    cudaGetSymbolAddress((void**)&qkv, g_qkv);
    cudaGetSymbolAddress((void**)&x1, g_x1);
    cudaGetSymbolAddress((void**)&xn2, g_xn2);
    cudaGetSymbolAddress((void**)&hbuf, g_hbuf);
    cudaGetSymbolAddress((void**)&wqkv, g_wqkv);
    cudaGetSymbolAddress((void**)&bqkv, g_bqkv);

    cudaFuncSetAttribute(attn_kernel,
                         cudaFuncAttributeMaxDynamicSharedMemorySize, ATTN_SMEM);

    // 0. pack QKV weights -> [512,1536]
    pack_qkv_kernel<<<768, 256>>>(Wq, Wk, Wv, bq, bk, bv, wqkv, bqkv);
    // 1. LN1
    ln_kernel<<<TOKENS, 128>>>(x, g1, be1, xn);
    // 2. fused QKV projection: [8192,512] @ [512,1536]
    mma_gemm<0, 0><<<dim3(3 * DM / BN, TOKENS / BM), 256>>>(
        xn, DM, wqkv, 3 * DM, bqkv, nullptr, qkv, 3 * DM, DM);
    // 3. sigmoid attention + residual -> x1
    attn_kernel<<<dim3(SEQ / 128, 4 * NH), 256, ATTN_SMEM>>>(qkv, x, x1);
    // 4. LN2
    ln_kernel<<<TOKENS, 128>>>(x1, g2, be2, xn2);
    // 5. FFN1 + ReLU
    mma_gemm<1, 0><<<dim3(DFF / BN, TOKENS / BM), 256>>>(
        xn2, DM, W1, DFF, b1, nullptr, hbuf, DFF, DM);
    // 6. FFN2 + bias + residual -> out
    mma_gemm<0, 1><<<dim3(DM / BN, TOKENS / BM), 256>>>(
        hbuf, DFF, W2, DM, b2, x1, out, DM, DFF);
}

// round 10
// speedup vs baseline: 3.2497x; 1.0928x over previous
#include <cuda_runtime.h>
#include <math.h>

#define TOKENS 8192
#define DM 512
#define DFF 2048
#define SEQ 2048
#define NH 8
#define DH 64

// Scratch (allocation-free rule: __device__ globals)
__device__ float g_xn[TOKENS * DM];
__device__ float g_qkv[TOKENS * 3 * DM];
__device__ float g_x1[TOKENS * DM];
__device__ float g_xn2[TOKENS * DM];
__device__ float g_hbuf[TOKENS * DFF];
__device__ float g_wqkv[DM * 3 * DM];
__device__ float g_bqkv[3 * DM];

// ---------------------------------------------------------------------------
// helpers
// ---------------------------------------------------------------------------
__device__ __forceinline__ unsigned f2tf(float x) {
    unsigned r;
    asm("cvt.rna.tf32.f32 %0, %1;" : "=r"(r) : "f"(x));
    return r;
}
__device__ __forceinline__ uint4 f2tf4(float4 v) {
    uint4 r;
    r.x = f2tf(v.x); r.y = f2tf(v.y); r.z = f2tf(v.z); r.w = f2tf(v.w);
    return r;
}
__device__ __forceinline__ void mma8(float* c, const unsigned* a, const unsigned* b) {
    asm volatile(
        "mma.sync.aligned.m16n8k8.row.col.f32.tf32.tf32.f32 "
        "{%0,%1,%2,%3}, {%4,%5,%6,%7}, {%8,%9}, {%0,%1,%2,%3};\n"
        : "+f"(c[0]), "+f"(c[1]), "+f"(c[2]), "+f"(c[3])
        : "r"(a[0]), "r"(a[1]), "r"(a[2]), "r"(a[3]), "r"(b[0]), "r"(b[1]));
}
__device__ __forceinline__ void cp16(void* smem, const void* g) {
    unsigned a = (unsigned)__cvta_generic_to_shared(smem);
    asm volatile("cp.async.cg.shared.global [%0], [%1], 16;" :: "r"(a), "l"(g));
}
__device__ __forceinline__ void cp_commit() {
    asm volatile("cp.async.commit_group;" ::: "memory");
}
template <int N>
__device__ __forceinline__ void cp_wait() {
    asm volatile("cp.async.wait_group %0;" :: "n"(N) : "memory");
}

// ---------------------------------------------------------------------------
// LayerNorm: one block (128 threads) per token row of 512
// ---------------------------------------------------------------------------
__global__ __launch_bounds__(128) void ln_kernel(
    const float* __restrict__ x, const float* __restrict__ g,
    const float* __restrict__ beta, float* __restrict__ out) {
    int row = blockIdx.x;
    int tid = threadIdx.x;
    const float4* xr = reinterpret_cast<const float4*>(x + (size_t)row * DM);
    float4 v = xr[tid];
    float s = v.x + v.y + v.z + v.w;
    float sq = v.x * v.x + v.y * v.y + v.z * v.z + v.w * v.w;
#pragma unroll
    for (int off = 16; off > 0; off >>= 1) {
        s  += __shfl_xor_sync(0xffffffffu, s, off);
        sq += __shfl_xor_sync(0xffffffffu, sq, off);
    }
    __shared__ float ss[4], ssq[4];
    int wid = tid >> 5, lane = tid & 31;
    if (lane == 0) { ss[wid] = s; ssq[wid] = sq; }
    __syncthreads();
    s  = ss[0] + ss[1] + ss[2] + ss[3];
    sq = ssq[0] + ssq[1] + ssq[2] + ssq[3];
    float mean = s * (1.0f / DM);
    float var = sq * (1.0f / DM) - mean * mean;
    float inv = rsqrtf(var + 1e-5f);
    float4 gv = reinterpret_cast<const float4*>(g)[tid];
    float4 bv = reinterpret_cast<const float4*>(beta)[tid];
    float4 o;
    o.x = (v.x - mean) * inv * gv.x + bv.x;
    o.y = (v.y - mean) * inv * gv.y + bv.y;
    o.z = (v.z - mean) * inv * gv.z + bv.z;
    o.w = (v.w - mean) * inv * gv.w + bv.w;
    reinterpret_cast<float4*>(out + (size_t)row * DM)[tid] = o;
}

// ---------------------------------------------------------------------------
// Pack Wq|Wk|Wv -> [512][1536] and biases -> [1536]
// ---------------------------------------------------------------------------
__global__ __launch_bounds__(256) void pack_qkv_kernel(
    const float* __restrict__ Wq, const float* __restrict__ Wk,
    const float* __restrict__ Wv, const float* __restrict__ bq,
    const float* __restrict__ bk, const float* __restrict__ bv,
    float* __restrict__ W, float* __restrict__ bias) {
    int idx = blockIdx.x * 256 + threadIdx.x;  // over 512*384 float4
    int row = idx / 384;
    int c4 = idx - row * 384;
    const float* src = (c4 < 128) ? Wq : (c4 < 256 ? Wk : Wv);
    int cc = (c4 & 127) * 4;
    float4 v = *reinterpret_cast<const float4*>(src + (size_t)row * DM + cc);
    *reinterpret_cast<float4*>(W + (size_t)row * (3 * DM) + c4 * 4) = v;
    if (idx < 384) {
        const float* bsrc = (idx < 128) ? bq : (idx < 256 ? bk : bv);
        *reinterpret_cast<float4*>(bias + idx * 4) =
            *reinterpret_cast<const float4*>(bsrc + (idx & 127) * 4);
    }
}

// ---------------------------------------------------------------------------
// tf32 tensor-core GEMM with cp.async double buffering.
// Block 128x128x32, 256 threads (8 warps, 2x4), warp tile 64x32 via m16n8k8.
// Operands fed as raw fp32 (HW truncation to tf32).
// ---------------------------------------------------------------------------
#define BM 128
#define BN 128
#define BK 32
#define LDA_S 36
#define LDB_S 136
#define GEMM_SMEM ((2 * (BM * LDA_S + BK * LDB_S)) * 4)

template <int RELU, int RES>
__global__ __launch_bounds__(256, 2) void mma_gemm(
    const float* __restrict__ A, int lda,
    const float* __restrict__ B, int ldb,
    const float* __restrict__ bias,
    const float* __restrict__ res,
    float* __restrict__ C, int ldc, int K) {
    extern __shared__ unsigned sg[];
    unsigned* Asb[2] = {sg, sg + BM * LDA_S};
    unsigned* Bsb[2] = {sg + 2 * BM * LDA_S, sg + 2 * BM * LDA_S + BK * LDB_S};

    int tid = threadIdx.x;
    int lane = tid & 31, wid = tid >> 5;
    int g = lane >> 2, tg = lane & 3;
    int wm = (wid >> 2) * 64;
    int wn = (wid & 3) * 32;
    int row0 = blockIdx.y * BM, col0 = blockIdx.x * BN;

    int a_r = tid >> 3, a_k4 = tid & 7;           // A load coords (+32 rows/pass)
    int b_kr = tid >> 5, b_n4 = tid & 31;         // B load coords (+8 rows/pass)
    const float* Ag = A + (size_t)(row0 + a_r) * lda + a_k4 * 4;
    const float* Bg = B + (size_t)b_kr * ldb + col0 + b_n4 * 4;

    float acc[4][4][4];
#pragma unroll
    for (int i = 0; i < 4; ++i)
#pragma unroll
        for (int j = 0; j < 4; ++j)
#pragma unroll
            for (int l = 0; l < 4; ++l) acc[i][j][l] = 0.0f;

#define LOAD_TILE(buf, k0)                                                     \
    {                                                                          \
        unsigned* As_ = Asb[buf];                                              \
        unsigned* Bs_ = Bsb[buf];                                              \
        _Pragma("unroll") for (int p = 0; p < 4; ++p)                          \
            cp16(&As_[(a_r + p * 32) * LDA_S + a_k4 * 4],                      \
                 Ag + (size_t)(p * 32) * lda + (k0));                          \
        _Pragma("unroll") for (int p = 0; p < 4; ++p)                          \
            cp16(&Bs_[(b_kr + p * 8) * LDB_S + b_n4 * 4],                      \
                 Bg + (size_t)((k0) + p * 8) * ldb);                           \
        cp_commit();                                                           \
    }

    LOAD_TILE(0, 0)
    LOAD_TILE(1, BK)
    cp_wait<1>();
    __syncthreads();

    int cur = 0;
    for (int k0 = 0; k0 < K; k0 += BK) {
        const unsigned* As = Asb[cur];
        const unsigned* Bs = Bsb[cur];
#pragma unroll
        for (int kk = 0; kk < 4; ++kk) {
            int kb = kk * 8;
            unsigned Af[4][4], Bf[4][2];
#pragma unroll
            for (int mt = 0; mt < 4; ++mt) {
                int r = wm + mt * 16 + g;
                Af[mt][0] = As[r * LDA_S + kb + tg];
                Af[mt][1] = As[(r + 8) * LDA_S + kb + tg];
                Af[mt][2] = As[r * LDA_S + kb + 4 + tg];
                Af[mt][3] = As[(r + 8) * LDA_S + kb + 4 + tg];
            }
#pragma unroll
            for (int nt = 0; nt < 4; ++nt) {
                int c = wn + nt * 8 + g;
                Bf[nt][0] = Bs[(kb + tg) * LDB_S + c];
                Bf[nt][1] = Bs[(kb + 4 + tg) * LDB_S + c];
            }
#pragma unroll
            for (int mt = 0; mt < 4; ++mt)
#pragma unroll
                for (int nt = 0; nt < 4; ++nt)
                    mma8(acc[mt][nt], Af[mt], Bf[nt]);
        }
        __syncthreads();
        int kp = k0 + 2 * BK;
        if (kp >= K) kp -= K;  // wrapped prefetch (harmless, keeps code uniform)
        LOAD_TILE(cur, kp)
        cp_wait<1>();
        __syncthreads();
        cur ^= 1;
    }
    cp_wait<0>();

#pragma unroll
    for (int nt = 0; nt < 4; ++nt) {
        int c = col0 + wn + nt * 8 + tg * 2;
        float b0 = bias[c], b1 = bias[c + 1];
#pragma unroll
        for (int mt = 0; mt < 4; ++mt) {
#pragma unroll
            for (int hh = 0; hh < 2; ++hh) {
                int r = row0 + wm + mt * 16 + g + hh * 8;
                float v0 = acc[mt][nt][hh * 2 + 0] + b0;
                float v1 = acc[mt][nt][hh * 2 + 1] + b1;
                if (RELU) { v0 = fmaxf(v0, 0.0f); v1 = fmaxf(v1, 0.0f); }
                if (RES) {
                    float2 rv = *reinterpret_cast<const float2*>(
                        res + (size_t)r * ldc + c);
                    v0 += rv.x; v1 += rv.y;
                }
                *reinterpret_cast<float2*>(C + (size_t)r * ldc + c) =
                    make_float2(v0, v1);
            }
        }
    }
}

// ---------------------------------------------------------------------------
// Sigmoid attention, tf32 mma, cp.async software pipeline:
//   while S=QK^T computes on K_t, V_t streams in;
//   while O+=P*V computes on V_t, K_{t+1} streams in.
// 2 barriers / 2 waits per t-tile. Residual x fused into epilogue.
// ---------------------------------------------------------------------------
#define LDQ 68
#define LDKV 72
#define LDS_S 68
#define ATTN_SMEM ((128 * LDQ + 2 * 64 * LDKV + 128 * LDS_S) * 4)

__global__ __launch_bounds__(256, 2) void attn_kernel(
    const float* __restrict__ qkv, const float* __restrict__ x,
    float* __restrict__ x1) {
    extern __shared__ unsigned sm[];
    unsigned* Qs = sm;                       // [128][LDQ]
    unsigned* Kb = sm + 128 * LDQ;           // [64][LDKV]
    unsigned* Vb = Kb + 64 * LDKV;           // [64][LDKV]
    unsigned* Ss = Vb + 64 * LDKV;           // [128][LDS_S]

    int tid = threadIdx.x;
    int lane = tid & 31, wid = tid >> 5;
    int g = lane >> 2, tg = lane & 3;
    int wm = (wid >> 2) * 64;   // warp q-row offset (2 warps)
    int wn = (wid & 3) * 16;    // warp col offset (4 warps)
    int s0 = blockIdx.x * 128;
    int b = blockIdx.y >> 3, h = blockIdx.y & 7;

    const float* qb = qkv + (size_t)b * SEQ * (3 * DM) + h * DH;
    const float* kb = qb + DM;
    const float* vb = qb + 2 * DM;

    int l_r = tid >> 4, l_d4 = tid & 15;  // KV tile load coords (+16 rows/pass)

#define LOAD_KV(dst, src, t)                                                   \
    {                                                                          \
        _Pragma("unroll") for (int p = 0; p < 4; ++p)                          \
            cp16(&(dst)[(l_r + p * 16) * LDKV + l_d4 * 4],                     \
                 (src) + (size_t)((t) + l_r + p * 16) * (3 * DM) + l_d4 * 4);  \
        cp_commit();                                                           \
    }

    LOAD_KV(Kb, kb, 0)
    LOAD_KV(Vb, vb, 0)

    // Q tile [128][64] -> Qs (tf32, regular loads; overlaps the cp.asyncs)
#pragma unroll
    for (int p = 0; p < 8; ++p) {
        int f = p * 256 + tid;
        int r = f >> 4, d4 = f & 15;
        float4 v = *reinterpret_cast<const float4*>(
            qb + (size_t)(s0 + r) * (3 * DM) + d4 * 4);
        *reinterpret_cast<uint4*>(&Qs[r * LDQ + d4 * 4]) = f2tf4(v);
    }

    float of[4][2][4];
#pragma unroll
    for (int i = 0; i < 4; ++i)
#pragma unroll
        for (int j = 0; j < 2; ++j)
#pragma unroll
            for (int l = 0; l < 4; ++l) of[i][j][l] = 0.0f;

    const float scale = 0.04419417382415922f;  // 1/sqrt(512)

    cp_wait<1>();       // K_0 landed (V_0 may still be in flight)
    __syncthreads();    // K_0 + Qs visible

    for (int t0 = 0; t0 < SEQ; t0 += 64) {
        // ---- S = Q @ K^T  (M=128 q, N=64 t, K=64 d) ----
        float sc[4][2][4];
#pragma unroll
        for (int i = 0; i < 4; ++i)
#pragma unroll
            for (int j = 0; j < 2; ++j)
#pragma unroll
                for (int l = 0; l < 4; ++l) sc[i][j][l] = 0.0f;
#pragma unroll
        for (int kk = 0; kk < 8; ++kk) {
            int kb8 = kk * 8;
            unsigned Af[4][4], Bf[2][2];
#pragma unroll
            for (int mt = 0; mt < 4; ++mt) {
                int r = wm + mt * 16 + g;
                Af[mt][0] = Qs[r * LDQ + kb8 + tg];
                Af[mt][1] = Qs[(r + 8) * LDQ + kb8 + tg];
                Af[mt][2] = Qs[r * LDQ + kb8 + 4 + tg];
                Af[mt][3] = Qs[(r + 8) * LDQ + kb8 + 4 + tg];
            }
#pragma unroll
            for (int nt = 0; nt < 2; ++nt) {
                int c = wn + nt * 8 + g;   // t index
                Bf[nt][0] = Kb[c * LDKV + kb8 + tg];
                Bf[nt][1] = Kb[c * LDKV + kb8 + 4 + tg];
            }
#pragma unroll
            for (int mt = 0; mt < 4; ++mt)
#pragma unroll
                for (int nt = 0; nt < 2; ++nt)
                    mma8(sc[mt][nt], Af[mt], Bf[nt]);
        }
        // sigmoid -> Ss (tf32)
#pragma unroll
        for (int mt = 0; mt < 4; ++mt)
#pragma unroll
            for (int nt = 0; nt < 2; ++nt) {
                int r = wm + mt * 16 + g;
                int c = wn + nt * 8 + tg * 2;
                uint2 p0, p1;
                p0.x = f2tf(1.0f / (1.0f + __expf(-sc[mt][nt][0] * scale)));
                p0.y = f2tf(1.0f / (1.0f + __expf(-sc[mt][nt][1] * scale)));
                p1.x = f2tf(1.0f / (1.0f + __expf(-sc[mt][nt][2] * scale)));
                p1.y = f2tf(1.0f / (1.0f + __expf(-sc[mt][nt][3] * scale)));
                *reinterpret_cast<uint2*>(&Ss[r * LDS_S + c]) = p0;
                *reinterpret_cast<uint2*>(&Ss[(r + 8) * LDS_S + c]) = p1;
            }

        cp_wait<0>();     // V_t landed
        __syncthreads();  // K reads done by all; Ss + V_t visible

        int tn = t0 + 64;
        if (tn >= SEQ) tn = 0;        // wrapped prefetch on last iter
        LOAD_KV(Kb, kb, tn)           // K_{t+1} streams during PV compute

        // ---- O += P @ V  (M=128 q, N=64 d, K=64 t) ----
#pragma unroll
        for (int kk = 0; kk < 8; ++kk) {
            int kb8 = kk * 8;
            unsigned Af[4][4], Bf[2][2];
#pragma unroll
            for (int mt = 0; mt < 4; ++mt) {
                int r = wm + mt * 16 + g;
                Af[mt][0] = Ss[r * LDS_S + kb8 + tg];
                Af[mt][1] = Ss[(r + 8) * LDS_S + kb8 + tg];
                Af[mt][2] = Ss[r * LDS_S + kb8 + 4 + tg];
                Af[mt][3] = Ss[(r + 8) * LDS_S + kb8 + 4 + tg];
            }
#pragma unroll
            for (int nt = 0; nt < 2; ++nt) {
                int c = wn + nt * 8 + g;   // d index
                Bf[nt][0] = Vb[(kb8 + tg) * LDKV + c];
                Bf[nt][1] = Vb[(kb8 + 4 + tg) * LDKV + c];
            }
#pragma unroll
            for (int mt = 0; mt < 4; ++mt)
#pragma unroll
                for (int nt = 0; nt < 2; ++nt)
                    mma8(of[mt][nt], Af[mt], Bf[nt]);
        }

        cp_wait<0>();     // K_{t+1} landed
        __syncthreads();  // V reads done by all; K_{t+1} visible
        LOAD_KV(Vb, vb, tn)           // V_{t+1} streams during next S compute
    }
    cp_wait<0>();  // drain before exit

    // Epilogue: x1 = x + attn_out
#pragma unroll
    for (int mt = 0; mt < 4; ++mt)
#pragma unroll
        for (int nt = 0; nt < 2; ++nt)
#pragma unroll
            for (int hh = 0; hh < 2; ++hh) {
                int r = s0 + wm + mt * 16 + g + hh * 8;
                int c = h * DH + wn + nt * 8 + tg * 2;
                size_t base = ((size_t)(b * SEQ) + r) * DM + c;
                float2 xv = *reinterpret_cast<const float2*>(x + base);
                float2 o = make_float2(xv.x + of[mt][nt][hh * 2 + 0],
                                       xv.y + of[mt][nt][hh * 2 + 1]);
                *reinterpret_cast<float2*>(x1 + base) = o;
            }
}

// ---------------------------------------------------------------------------
extern "C" void kernel_launch(void* const* d_in, const int* in_sizes, int n_in,
                              void* d_out, int out_size) {
    const float* x  = (const float*)d_in[0];
    const float* Wq = (const float*)d_in[1];
    const float* bq = (const float*)d_in[2];
    const float* Wk = (const float*)d_in[3];
    const float* bk = (const float*)d_in[4];
    const float* Wv = (const float*)d_in[5];
    const float* bv = (const float*)d_in[6];
    const float* W1 = (const float*)d_in[7];
    const float* b1 = (const float*)d_in[8];
    const float* W2 = (const float*)d_in[9];
    const float* b2 = (const float*)d_in[10];
    const float* g1 = (const float*)d_in[11];
    const float* be1 = (const float*)d_in[12];
    const float* g2 = (const float*)d_in[13];
    const float* be2 = (const float*)d_in[14];
    float* out = (float*)d_out;

    float *xn, *qkv, *x1, *xn2, *hbuf, *wqkv, *bqkv;
    cudaGetSymbolAddress((void**)&xn, g_xn);
    cudaGetSymbolAddress((void**)&qkv, g_qkv);
    cudaGetSymbolAddress((void**)&x1, g_x1);
    cudaGetSymbolAddress((void**)&xn2, g_xn2);
    cudaGetSymbolAddress((void**)&hbuf, g_hbuf);
    cudaGetSymbolAddress((void**)&wqkv, g_wqkv);
    cudaGetSymbolAddress((void**)&bqkv, g_bqkv);

    cudaFuncSetAttribute(attn_kernel,
                         cudaFuncAttributeMaxDynamicSharedMemorySize, ATTN_SMEM);
    cudaFuncSetAttribute(mma_gemm<0, 0>,
                         cudaFuncAttributeMaxDynamicSharedMemorySize, GEMM_SMEM);
    cudaFuncSetAttribute(mma_gemm<1, 0>,
                         cudaFuncAttributeMaxDynamicSharedMemorySize, GEMM_SMEM);
    cudaFuncSetAttribute(mma_gemm<0, 1>,
                         cudaFuncAttributeMaxDynamicSharedMemorySize, GEMM_SMEM);

    // 0. pack QKV weights -> [512,1536]
    pack_qkv_kernel<<<768, 256>>>(Wq, Wk, Wv, bq, bk, bv, wqkv, bqkv);
    // 1. LN1
    ln_kernel<<<TOKENS, 128>>>(x, g1, be1, xn);
    // 2. fused QKV projection: [8192,512] @ [512,1536]
    mma_gemm<0, 0><<<dim3(3 * DM / BN, TOKENS / BM), 256, GEMM_SMEM>>>(
        xn, DM, wqkv, 3 * DM, bqkv, nullptr, qkv, 3 * DM, DM);
    // 3. sigmoid attention + residual -> x1
    attn_kernel<<<dim3(SEQ / 128, 4 * NH), 256, ATTN_SMEM>>>(qkv, x, x1);
    // 4. LN2
    ln_kernel<<<TOKENS, 128>>>(x1, g2, be2, xn2);
    // 5. FFN1 + ReLU
    mma_gemm<1, 0><<<dim3(DFF / BN, TOKENS / BM), 256, GEMM_SMEM>>>(
        xn2, DM, W1, DFF, b1, nullptr, hbuf, DFF, DM);
    // 6. FFN2 + bias + residual -> out
    mma_gemm<0, 1><<<dim3(DM / BN, TOKENS / BM), 256, GEMM_SMEM>>>(
        hbuf, DFF, W2, DM, b2, x1, out, DM, DFF);
}